// round 1
// baseline (speedup 1.0000x reference)
#include <cuda_runtime.h>
#include <cuda_bf16.h>
#include <math.h>

// Problem constants
#define G_DIM 4
#define S_DIM 2048
#define D_DIM 1024
#define E_DIM 32
#define TOPK  4
#define CAP   256
#define NTOK  (G_DIM * S_DIM)          // 8192
#define COMBINE_ELEMS 66846720ull      // 4*2048*32*255

// Scratch (no cudaMalloc allowed)
__device__ float g_logits[NTOK * E_DIM];
__device__ float g_gates[NTOK * TOPK];
__device__ int   g_idx[NTOK * TOPK];
__device__ int   g_pos[NTOK * TOPK];

// ---------------------------------------------------------------------------
// GEMM: logits[t][e] = sum_d x[t][d] * W[d][e] + b[e]
// M=8192, N=32, K=1024. BM=64, BK=64, 128 CTAs x 256 threads.
// Thread tile: 2 tokens x 4 experts.
// ---------------------------------------------------------------------------
#define BM 64
#define BK 64

__global__ __launch_bounds__(256) void gemm_kernel(
    const float* __restrict__ x, const float* __restrict__ W,
    const float* __restrict__ b)
{
    __shared__ float xs[BM][BK + 4];   // pad to 68 floats/row (16B-aligned rows)
    __shared__ float Ws[BK][E_DIM];

    const int tid = threadIdx.x;
    const int m0  = blockIdx.x * BM;
    const int ty  = tid >> 3;          // 0..31 -> 2 tokens each
    const int tx  = tid & 7;           // 0..7  -> 4 experts each
    const int tm  = ty * 2;
    const int te  = tx * 4;

    float acc[2][4] = {};

    for (int kt = 0; kt < D_DIM; kt += BK) {
        // load x tile: 64 tokens x 64 k = 1024 float4, 4 per thread
        #pragma unroll
        for (int i = 0; i < 4; i++) {
            int fidx = tid + i * 256;
            int m  = fidx >> 4;
            int k4 = (fidx & 15) << 2;
            float4 gx = *(const float4*)&x[(size_t)(m0 + m) * D_DIM + kt + k4];
            *(float4*)&xs[m][k4] = gx;
        }
        // load W tile: 64 k x 32 e = 512 float4, 2 per thread
        #pragma unroll
        for (int i = 0; i < 2; i++) {
            int fidx = tid + i * 256;
            int k  = fidx >> 3;
            int e4 = (fidx & 7) << 2;
            *(float4*)&Ws[k][e4] = *(const float4*)&W[(size_t)(kt + k) * E_DIM + e4];
        }
        __syncthreads();

        #pragma unroll
        for (int k = 0; k < BK; k += 4) {
            float4 xa0 = *(float4*)&xs[tm][k];
            float4 xa1 = *(float4*)&xs[tm + 1][k];
            float4 w0  = *(float4*)&Ws[k][te];
            float4 w1  = *(float4*)&Ws[k + 1][te];
            float4 w2  = *(float4*)&Ws[k + 2][te];
            float4 w3  = *(float4*)&Ws[k + 3][te];
            float a0[4] = {xa0.x, xa0.y, xa0.z, xa0.w};
            float a1[4] = {xa1.x, xa1.y, xa1.z, xa1.w};
            float4 wv[4] = {w0, w1, w2, w3};
            #pragma unroll
            for (int kk = 0; kk < 4; kk++) {
                acc[0][0] = fmaf(a0[kk], wv[kk].x, acc[0][0]);
                acc[0][1] = fmaf(a0[kk], wv[kk].y, acc[0][1]);
                acc[0][2] = fmaf(a0[kk], wv[kk].z, acc[0][2]);
                acc[0][3] = fmaf(a0[kk], wv[kk].w, acc[0][3]);
                acc[1][0] = fmaf(a1[kk], wv[kk].x, acc[1][0]);
                acc[1][1] = fmaf(a1[kk], wv[kk].y, acc[1][1]);
                acc[1][2] = fmaf(a1[kk], wv[kk].z, acc[1][2]);
                acc[1][3] = fmaf(a1[kk], wv[kk].w, acc[1][3]);
            }
        }
        __syncthreads();
    }

    float b0 = b[te], b1 = b[te + 1], b2 = b[te + 2], b3 = b[te + 3];
    #pragma unroll
    for (int r = 0; r < 2; r++) {
        int t = m0 + tm + r;
        float4 o = make_float4(acc[r][0] + b0, acc[r][1] + b1,
                               acc[r][2] + b2, acc[r][3] + b3);
        *(float4*)&g_logits[(size_t)t * E_DIM + te] = o;
    }
}

// ---------------------------------------------------------------------------
// Softmax + top-4 per token. One warp per token, lane = expert.
// jax.lax.top_k ties -> lowest index first: strict-greater argmax, ties prefer
// smaller index, iterated 4x.
// ---------------------------------------------------------------------------
__global__ __launch_bounds__(256) void topk_kernel()
{
    int warp = (blockIdx.x * blockDim.x + threadIdx.x) >> 5;
    int lane = threadIdx.x & 31;
    if (warp >= NTOK) return;

    float v = g_logits[(size_t)warp * E_DIM + lane];

    float m = v;
    #pragma unroll
    for (int o = 16; o; o >>= 1) m = fmaxf(m, __shfl_xor_sync(0xffffffffu, m, o));
    float p = expf(v - m);
    float s = p;
    #pragma unroll
    for (int o = 16; o; o >>= 1) s += __shfl_xor_sync(0xffffffffu, s, o);
    p /= s;

    float pw = p;
    #pragma unroll
    for (int j = 0; j < TOPK; j++) {
        float bv = pw; int bi = lane;
        #pragma unroll
        for (int o = 16; o; o >>= 1) {
            float ov = __shfl_xor_sync(0xffffffffu, bv, o);
            int   oi = __shfl_xor_sync(0xffffffffu, bi, o);
            if (ov > bv || (ov == bv && oi < bi)) { bv = ov; bi = oi; }
        }
        if (lane == 0) {
            g_gates[warp * TOPK + j] = bv;
            g_idx[warp * TOPK + j]   = bi;
        }
        if (lane == bi) pw = -1.0f;
    }
}

// ---------------------------------------------------------------------------
// Sequential position scan. cumsum is over S per (g, k-slot, expert).
// One warp per (g,k). 32 tokens per ballot step via __match_any_sync.
// pos = running count including self (>= 1).
// ---------------------------------------------------------------------------
__global__ void scan_kernel()
{
    int gk = blockIdx.x;           // 0..15
    int g = gk >> 2, k = gk & 3;
    int lane = threadIdx.x;

    __shared__ int cnt[E_DIM];
    cnt[lane] = 0;
    __syncwarp();

    for (int s0 = 0; s0 < S_DIM; s0 += 32) {
        int t = g * S_DIM + s0 + lane;
        int e = g_idx[t * TOPK + k];
        unsigned mask = __match_any_sync(0xffffffffu, e);
        int rank = __popc(mask & ((1u << lane) - 1u));
        int base = cnt[e];
        __syncwarp();
        g_pos[t * TOPK + k] = base + rank + 1;
        if (rank == 0) cnt[e] = base + __popc(mask);
        __syncwarp();
    }
}

// ---------------------------------------------------------------------------
// Scatter gates into zeroed output. Valid when pos < CAP (pos in [1,255]),
// combine index = pos - 1. Mask region (if present) gets 1.0f.
// ---------------------------------------------------------------------------
__global__ void scatter_kernel(float* __restrict__ out, int has_mask)
{
    int i = blockIdx.x * blockDim.x + threadIdx.x;   // 0..32767
    if (i >= NTOK * TOPK) return;
    int p = g_pos[i];
    if (p >= CAP) return;                            // pos >= 256 invalid
    int t = i >> 2;
    int e = g_idx[i];
    size_t off = ((size_t)t * E_DIM + e) * (CAP - 1) + (p - 1);
    out[off] = g_gates[i];
    if (has_mask) out[COMBINE_ELEMS + off] = 1.0f;
}

// ---------------------------------------------------------------------------
extern "C" void kernel_launch(void* const* d_in, const int* in_sizes, int n_in,
                              void* d_out, int out_size)
{
    const float* x = (const float*)d_in[0];
    const float* W = (const float*)d_in[1];
    const float* b = (const float*)d_in[2];
    float* out = (float*)d_out;

    int has_mask = ((size_t)out_size >= 2ull * COMBINE_ELEMS) ? 1 : 0;

    // Zero the whole output (covers combine, mask, and loss=0).
    cudaMemsetAsync(d_out, 0, (size_t)out_size * sizeof(float), 0);

    gemm_kernel<<<NTOK / BM, 256>>>(x, W, b);
    topk_kernel<<<(NTOK * 32) / 256, 256>>>();
    scan_kernel<<<G_DIM * TOPK, 32>>>();
    scatter_kernel<<<(NTOK * TOPK) / 256, 256>>>(out, has_mask);
}